// round 7
// baseline (speedup 1.0000x reference)
#include <cuda_runtime.h>
#include <cstdint>

// Cost volume, B=8 C=128 H=128 W=256, d=4 -> 81 shifts.
// out[b, i*9+j, h, w] = (1/C) * sum_c f1[b,c,h,w] * f2[b,c,h+i-4,w+j-4] (zero pad)
//
// v5 = v4 + packed fp32 math (fma.rn.f32x2):
//   4 w-pixels/thread as two (lo,hi) pixel pairs, 54 ull accumulators,
//   window pairs built from aligned ull views (5 mov.b64 repacks per i-row).
//   3-stage cp.async pipeline and LDS.128 layout unchanged from v4.

typedef unsigned long long ull;

namespace {
constexpr int Bc = 8;
constexpr int Cc = 128;
constexpr int Hc = 128;
constexpr int Wc = 256;
constexpr int Dd = 4;
constexpr int Ss = 9;
constexpr int NS = 81;
constexpr int TH = 16;
constexpr int TW = 32;
constexpr int F2H = TH + 2 * Dd;    // 24
constexpr int F2W = TW + 2 * Dd;    // 40 floats row stride (160B, 16B multiple)
constexpr int HW = Hc * Wc;
constexpr int NF2 = F2H * (F2W / 4);   // 240 float4 chunks per channel
constexpr int NF1 = TH * TW / 4;       // 128 float4 chunks per channel
constexpr int NT = 384;
}

__device__ __forceinline__ void fma2(ull& acc, ull a, ull b) {
    asm("fma.rn.f32x2 %0, %1, %2, %0;" : "+l"(acc) : "l"(a), "l"(b));
}
// pair = (hi word of a, lo word of b)  ->  (w[2m+1], w[2m+2])
__device__ __forceinline__ ull mkpair(ull a, ull b) {
    ull r;
    asm("mov.b64 %0, {%1, %2};"
        : "=l"(r) : "r"((unsigned)(a >> 32)), "r"((unsigned)b));
    return r;
}
__device__ __forceinline__ float lo32(ull v) { return __uint_as_float((unsigned)v); }
__device__ __forceinline__ float hi32(ull v) { return __uint_as_float((unsigned)(v >> 32)); }

__global__ __launch_bounds__(NT, 1)
void cost_volume_kernel(const float* __restrict__ f1,
                        const float* __restrict__ f2,
                        float* __restrict__ out) {
    __shared__ __align__(16) float sf2[3][F2H * F2W];  // 11.25 KB
    __shared__ __align__(16) float sf1[3][TH * TW];    // 6 KB

    const int tid = threadIdx.x;
    const int grp = tid / 128;          // i-group: handles i = 3*grp + ii
    const int gt  = tid % 128;
    const int tx  = gt & 7;             // quad column (w = w0 + 4*tx + p)
    const int r   = gt >> 3;            // output row within tile, 0..15
    const int w0 = blockIdx.x * TW;
    const int h0 = blockIdx.y * TH;
    const int b  = blockIdx.z;

    // ---- loader roles: tid<240 -> f2 chunks, 240..367 -> f1 chunks ----
    const bool isF2 = (tid < NF2);
    const bool isF1 = (tid >= NF2) && (tid < NF2 + NF1);
    size_t src = 0; int sts = 0, srcsz = 16;
    if (isF2) {
        const int lr = tid / 10, lc = tid % 10;
        const int gh = h0 - Dd + lr;
        const int gw = w0 - Dd + 4 * lc;          // 4-aligned; halo chunks fully in/out
        const bool valid = ((unsigned)gh < (unsigned)Hc) &&
                           ((unsigned)gw < (unsigned)Wc);
        src   = (((size_t)b * Cc) * Hc + (valid ? gh : 0)) * (size_t)Wc
              + (valid ? gw : 0);
        sts   = lr * F2W + 4 * lc;
        srcsz = valid ? 16 : 0;                   // 0 -> zero-fill (padding)
    } else if (isF1) {
        const int L = tid - NF2;
        const int lr = L / 8, lc = L % 8;
        src = (((size_t)b * Cc) * Hc + (h0 + lr)) * (size_t)Wc + (w0 + 4 * lc);
        sts = lr * TW + 4 * lc;
    }

    auto issue = [&](int ch, int buf) {
        if (isF2) {
            uint32_t d = (uint32_t)__cvta_generic_to_shared(&sf2[buf][sts]);
            asm volatile("cp.async.cg.shared.global [%0], [%1], 16, %2;"
                         :: "r"(d), "l"(f2 + src + (size_t)ch * HW), "r"(srcsz));
        } else if (isF1) {
            uint32_t d = (uint32_t)__cvta_generic_to_shared(&sf1[buf][sts]);
            asm volatile("cp.async.cg.shared.global [%0], [%1], 16;"
                         :: "r"(d), "l"(f1 + src + (size_t)ch * HW));
        }
    };

    // ---- prologue: stage channels 0 and 1 ----
    issue(0, 0);
    asm volatile("cp.async.commit_group;" ::: "memory");
    issue(1, 1);
    asm volatile("cp.async.commit_group;" ::: "memory");

    // 54 packed accumulators: [ii*9+j], lanes = pixel pairs (0,1) and (2,3)
    ull acc01[27], acc23[27];
#pragma unroll
    for (int s = 0; s < 27; ++s) { acc01[s] = 0ull; acc23[s] = 0ull; }

#pragma unroll 1
    for (int ch = 0; ch < Cc; ++ch) {
        asm volatile("cp.async.wait_group 1;" ::: "memory");
        __syncthreads();

        // stage ch+2 into buffer (ch+2)%3 (its readers finished before the barrier)
        if (ch + 2 < Cc) issue(ch + 2, (ch + 2) % 3);
        asm volatile("cp.async.commit_group;" ::: "memory");

        const int buf = ch % 3;
        // f1 quad as two packed pairs (LDS.128)
        const ulonglong2 f1q = *(const ulonglong2*)&sf1[buf][r * TW + 4 * tx];
        const ull f01 = f1q.x;   // (f1.x, f1.y)
        const ull f23 = f1q.y;   // (f1.z, f1.w)

#pragma unroll
        for (int ii = 0; ii < 3; ++ii) {
            // shift row i = 3*grp + ii; smem f2 row = r + i
            const float* wr = &sf2[buf][(r + 3 * grp + ii) * F2W + 4 * tx];
            const ulonglong2 q0 = *(const ulonglong2*)(wr);       // LDS.128
            const ulonglong2 q1 = *(const ulonglong2*)(wr + 4);
            const ulonglong2 q2 = *(const ulonglong2*)(wr + 8);
            // pr[k] = (w[k], w[k+1]); even k free, odd k via mov.b64
            ull pr[11];
            pr[0]  = q0.x;  pr[2]  = q0.y;  pr[4] = q1.x;
            pr[6]  = q1.y;  pr[8]  = q2.x;  pr[10] = q2.y;
            pr[1]  = mkpair(q0.x, q0.y);
            pr[3]  = mkpair(q0.y, q1.x);
            pr[5]  = mkpair(q1.x, q1.y);
            pr[7]  = mkpair(q1.y, q2.x);
            pr[9]  = mkpair(q2.x, q2.y);
#pragma unroll
            for (int j = 0; j < Ss; ++j) {
                fma2(acc01[ii * Ss + j], f01, pr[j]);      // pixels 0,1: w[j], w[j+1]
                fma2(acc23[ii * Ss + j], f23, pr[j + 2]);  // pixels 2,3: w[j+2], w[j+3]
            }
        }
    }

    // ---- epilogue: 27 float4 stores per thread, coalesced ----
    const float sc = 1.0f / (float)Cc;
    float* ob = out + (((size_t)b * NS) * Hc + (h0 + r)) * (size_t)Wc + (w0 + 4 * tx);
#pragma unroll
    for (int ii = 0; ii < 3; ++ii) {
#pragma unroll
        for (int j = 0; j < Ss; ++j) {
            const int s = (3 * grp + ii) * Ss + j;
            const ull a = acc01[ii * Ss + j];
            const ull c = acc23[ii * Ss + j];
            float4 v;
            v.x = lo32(a) * sc;
            v.y = hi32(a) * sc;
            v.z = lo32(c) * sc;
            v.w = hi32(c) * sc;
            *(float4*)(ob + (size_t)s * HW) = v;
        }
    }
}

extern "C" void kernel_launch(void* const* d_in, const int* in_sizes, int n_in,
                              void* d_out, int out_size) {
    const float* f1 = (const float*)d_in[0];
    const float* f2 = (const float*)d_in[1];
    float* out = (float*)d_out;
    dim3 grid(Wc / TW, Hc / TH, Bc);   // 8 x 8 x 8 = 512 blocks
    cost_volume_kernel<<<grid, NT>>>(f1, f2, out);
}

// round 9
// speedup vs baseline: 1.3801x; 1.3801x over previous
#include <cuda_runtime.h>
#include <cstdint>

// Cost volume, B=8 C=128 H=128 W=256, d=4 -> 81 shifts.
// out[b, i*9+j, h, w] = (1/C) * sum_c f1[b,c,h,w] * f2[b,c,h+i-4,w+j-4] (zero pad)
//
// v7 = v4 (best, 227us) with 2 channels per pipeline stage:
//   - 64 barriers instead of 128 (amortized BAR + skew)
//   - two independent per-channel FMA/LDS chains per stage (better ILP at
//     3 warps/SMSP)
//   - scalar FFMA only (f32x2 experiment regressed: mov.b64 repacks turned
//     the kernel ALU-bound)

namespace {
constexpr int Bc = 8;
constexpr int Cc = 128;
constexpr int Hc = 128;
constexpr int Wc = 256;
constexpr int Dd = 4;
constexpr int Ss = 9;
constexpr int NS = 81;
constexpr int TH = 16;
constexpr int TW = 32;
constexpr int F2H = TH + 2 * Dd;    // 24
constexpr int F2W = TW + 2 * Dd;    // 40 floats row stride (160B, 16B multiple)
constexpr int HW = Hc * Wc;
constexpr int NF2 = F2H * (F2W / 4);   // 240 float4 chunks per channel
constexpr int NF1 = TH * TW / 4;       // 128 float4 chunks per channel
constexpr int NT = 384;
constexpr int NSTG = Cc / 2;           // 64 stages, 2 channels each
}

__global__ __launch_bounds__(NT, 1)
void cost_volume_kernel(const float* __restrict__ f1,
                        const float* __restrict__ f2,
                        float* __restrict__ out) {
    __shared__ __align__(16) float sf2[3][2][F2H * F2W];  // 22.5 KB
    __shared__ __align__(16) float sf1[3][2][TH * TW];    // 12 KB

    const int tid = threadIdx.x;
    const int grp = tid / 128;          // i-group: handles i = 3*grp + ii
    const int gt  = tid % 128;
    const int tx  = gt & 7;             // quad column (w = w0 + 4*tx + p)
    const int r   = gt >> 3;            // output row within tile, 0..15
    const int w0 = blockIdx.x * TW;
    const int h0 = blockIdx.y * TH;
    const int b  = blockIdx.z;

    // ---- loader roles: tid<240 -> f2 chunks, 240..367 -> f1 chunks ----
    const bool isF2 = (tid < NF2);
    const bool isF1 = (tid >= NF2) && (tid < NF2 + NF1);
    size_t src = 0; int sts = 0, srcsz = 16;
    if (isF2) {
        const int lr = tid / 10, lc = tid % 10;
        const int gh = h0 - Dd + lr;
        const int gw = w0 - Dd + 4 * lc;          // 4-aligned; halo chunks fully in/out
        const bool valid = ((unsigned)gh < (unsigned)Hc) &&
                           ((unsigned)gw < (unsigned)Wc);
        src   = (((size_t)b * Cc) * Hc + (valid ? gh : 0)) * (size_t)Wc
              + (valid ? gw : 0);
        sts   = lr * F2W + 4 * lc;
        srcsz = valid ? 16 : 0;                   // 0 -> zero-fill (padding)
    } else if (isF1) {
        const int L = tid - NF2;
        const int lr = L / 8, lc = L % 8;
        src = (((size_t)b * Cc) * Hc + (h0 + lr)) * (size_t)Wc + (w0 + 4 * lc);
        sts = lr * TW + 4 * lc;
    }

    // stage st = channels (2*st, 2*st+1) into buffer buf
    auto issue = [&](int st, int buf) {
        if (isF2) {
            const float* s0 = f2 + src + (size_t)(2 * st) * HW;
#pragma unroll
            for (int cc = 0; cc < 2; ++cc) {
                uint32_t d = (uint32_t)__cvta_generic_to_shared(&sf2[buf][cc][sts]);
                asm volatile("cp.async.cg.shared.global [%0], [%1], 16, %2;"
                             :: "r"(d), "l"(s0 + (size_t)cc * HW), "r"(srcsz));
            }
        } else if (isF1) {
            const float* s0 = f1 + src + (size_t)(2 * st) * HW;
#pragma unroll
            for (int cc = 0; cc < 2; ++cc) {
                uint32_t d = (uint32_t)__cvta_generic_to_shared(&sf1[buf][cc][sts]);
                asm volatile("cp.async.cg.shared.global [%0], [%1], 16;"
                             :: "r"(d), "l"(s0 + (size_t)cc * HW));
            }
        }
    };

    // ---- prologue: stage 0 and 1 ----
    issue(0, 0);
    asm volatile("cp.async.commit_group;" ::: "memory");
    issue(1, 1);
    asm volatile("cp.async.commit_group;" ::: "memory");

    // 108 accumulators: acc[ii*36 + j*4 + p]
    float acc[108];
#pragma unroll
    for (int s = 0; s < 108; ++s) acc[s] = 0.0f;

    const int f1off = r * TW + 4 * tx;
    const int f2off = (r + 3 * grp) * F2W + 4 * tx;

#pragma unroll 1
    for (int st = 0; st < NSTG; ++st) {
        asm volatile("cp.async.wait_group 1;" ::: "memory");
        __syncthreads();

        // stage st+2 into buffer (st+2)%3 (its readers finished before the barrier)
        if (st + 2 < NSTG) issue(st + 2, (st + 2) % 3);
        asm volatile("cp.async.commit_group;" ::: "memory");

        const int buf = st % 3;
#pragma unroll
        for (int cc = 0; cc < 2; ++cc) {
            const float4 f1v = *(const float4*)&sf1[buf][cc][f1off];  // LDS.128
            const float* base = &sf2[buf][cc][f2off];
#pragma unroll
            for (int ii = 0; ii < 3; ++ii) {
                const float* wr = base + ii * F2W;
                float w[12];
                *(float4*)&w[0] = *(const float4*)(wr);       // LDS.128, conflict-free
                *(float4*)&w[4] = *(const float4*)(wr + 4);
                *(float4*)&w[8] = *(const float4*)(wr + 8);
#pragma unroll
                for (int j = 0; j < Ss; ++j) {
                    acc[ii * 36 + j * 4 + 0] = fmaf(f1v.x, w[j + 0], acc[ii * 36 + j * 4 + 0]);
                    acc[ii * 36 + j * 4 + 1] = fmaf(f1v.y, w[j + 1], acc[ii * 36 + j * 4 + 1]);
                    acc[ii * 36 + j * 4 + 2] = fmaf(f1v.z, w[j + 2], acc[ii * 36 + j * 4 + 2]);
                    acc[ii * 36 + j * 4 + 3] = fmaf(f1v.w, w[j + 3], acc[ii * 36 + j * 4 + 3]);
                }
            }
        }
    }

    // ---- epilogue: 27 float4 stores per thread, coalesced ----
    const float sc = 1.0f / (float)Cc;
    float* ob = out + (((size_t)b * NS) * Hc + (h0 + r)) * (size_t)Wc + (w0 + 4 * tx);
#pragma unroll
    for (int ii = 0; ii < 3; ++ii) {
#pragma unroll
        for (int j = 0; j < Ss; ++j) {
            const int s = (3 * grp + ii) * Ss + j;
            float4 v;
            v.x = acc[ii * 36 + j * 4 + 0] * sc;
            v.y = acc[ii * 36 + j * 4 + 1] * sc;
            v.z = acc[ii * 36 + j * 4 + 2] * sc;
            v.w = acc[ii * 36 + j * 4 + 3] * sc;
            *(float4*)(ob + (size_t)s * HW) = v;
        }
    }
}

extern "C" void kernel_launch(void* const* d_in, const int* in_sizes, int n_in,
                              void* d_out, int out_size) {
    const float* f1 = (const float*)d_in[0];
    const float* f2 = (const float*)d_in[1];
    float* out = (float*)d_out;
    dim3 grid(Wc / TW, Hc / TH, Bc);   // 8 x 8 x 8 = 512 blocks
    cost_volume_kernel<<<grid, NT>>>(f1, f2, out);
}

// round 13
// speedup vs baseline: 1.4990x; 1.0862x over previous
#include <cuda_runtime.h>
#include <cstdint>

// Cost volume, B=8 C=128 H=128 W=256, d=4 -> 81 shifts.
// out[b, i*9+j, h, w] = (1/C) * sum_c f1[b,c,h,w] * f2[b,c,h+i-4,w+j-4] (zero pad)
//
// v9 = v7 (207us) with 4 channels per pipeline stage:
//   - 32 barriers instead of 64 (per-stage BAR/skew/LDS-head amortized 2x more)
//   - 4 independent per-channel FMA/LDS chains per stage
//   - smem 69KB -> dynamic shared memory (3 bufs x 4 channels)
//   - scalar FFMA only (f32x2 proven ALU-bound regression)

namespace {
constexpr int Bc = 8;
constexpr int Cc = 128;
constexpr int Hc = 128;
constexpr int Wc = 256;
constexpr int Dd = 4;
constexpr int Ss = 9;
constexpr int NS = 81;
constexpr int TH = 16;
constexpr int TW = 32;
constexpr int F2H = TH + 2 * Dd;    // 24
constexpr int F2W = TW + 2 * Dd;    // 40 floats row stride (160B, 16B multiple)
constexpr int HW = Hc * Wc;
constexpr int NF2 = F2H * (F2W / 4);   // 240 float4 chunks per channel
constexpr int NF1 = TH * TW / 4;       // 128 float4 chunks per channel
constexpr int NT = 384;
constexpr int CPS = 4;                 // channels per stage
constexpr int NSTG = Cc / CPS;         // 32 stages
constexpr int F2SZ = F2H * F2W;        // 960 floats
constexpr int F1SZ = TH * TW;          // 512 floats
constexpr int CHSZ = F2SZ + F1SZ;      // 1472 floats per channel slot
constexpr int SMEM_BYTES = 3 * CPS * CHSZ * 4;   // 70656 B
}

__global__ __launch_bounds__(NT, 1)
void cost_volume_kernel(const float* __restrict__ f1,
                        const float* __restrict__ f2,
                        float* __restrict__ out) {
    extern __shared__ __align__(16) float smem[];
    // layout: slot(buf, cc) = smem + (buf*CPS + cc)*CHSZ ; f2 first, then f1

    const int tid = threadIdx.x;
    const int grp = tid / 128;          // i-group: handles i = 3*grp + ii
    const int gt  = tid % 128;
    const int tx  = gt & 7;             // quad column (w = w0 + 4*tx + p)
    const int r   = gt >> 3;            // output row within tile, 0..15
    const int w0 = blockIdx.x * TW;
    const int h0 = blockIdx.y * TH;
    const int b  = blockIdx.z;

    // ---- loader roles: tid<240 -> f2 chunks, 240..367 -> f1 chunks ----
    const bool isF2 = (tid < NF2);
    const bool isF1 = (tid >= NF2) && (tid < NF2 + NF1);
    size_t src = 0; int sts = 0, srcsz = 16;
    if (isF2) {
        const int lr = tid / 10, lc = tid % 10;
        const int gh = h0 - Dd + lr;
        const int gw = w0 - Dd + 4 * lc;          // 4-aligned; halo chunks fully in/out
        const bool valid = ((unsigned)gh < (unsigned)Hc) &&
                           ((unsigned)gw < (unsigned)Wc);
        src   = (((size_t)b * Cc) * Hc + (valid ? gh : 0)) * (size_t)Wc
              + (valid ? gw : 0);
        sts   = lr * F2W + 4 * lc;                // within f2 part of slot
        srcsz = valid ? 16 : 0;                   // 0 -> zero-fill (padding)
    } else if (isF1) {
        const int L = tid - NF2;
        const int lr = L / 8, lc = L % 8;
        src = (((size_t)b * Cc) * Hc + (h0 + lr)) * (size_t)Wc + (w0 + 4 * lc);
        sts = F2SZ + lr * TW + 4 * lc;            // f1 part of slot
    }

    // stage st = channels [CPS*st, CPS*st+CPS) into buffer buf
    auto issue = [&](int st, int buf) {
        if (isF2) {
            const float* s0 = f2 + src + (size_t)(CPS * st) * HW;
#pragma unroll
            for (int cc = 0; cc < CPS; ++cc) {
                uint32_t d = (uint32_t)__cvta_generic_to_shared(
                    &smem[(buf * CPS + cc) * CHSZ + sts]);
                asm volatile("cp.async.cg.shared.global [%0], [%1], 16, %2;"
                             :: "r"(d), "l"(s0 + (size_t)cc * HW), "r"(srcsz));
            }
        } else if (isF1) {
            const float* s0 = f1 + src + (size_t)(CPS * st) * HW;
#pragma unroll
            for (int cc = 0; cc < CPS; ++cc) {
                uint32_t d = (uint32_t)__cvta_generic_to_shared(
                    &smem[(buf * CPS + cc) * CHSZ + sts]);
                asm volatile("cp.async.cg.shared.global [%0], [%1], 16;"
                             :: "r"(d), "l"(s0 + (size_t)cc * HW));
            }
        }
    };

    // ---- prologue: stage 0 and 1 ----
    issue(0, 0);
    asm volatile("cp.async.commit_group;" ::: "memory");
    issue(1, 1);
    asm volatile("cp.async.commit_group;" ::: "memory");

    // 108 accumulators: acc[ii*36 + j*4 + p]
    float acc[108];
#pragma unroll
    for (int s = 0; s < 108; ++s) acc[s] = 0.0f;

    const int f1off = F2SZ + r * TW + 4 * tx;
    const int f2off = (r + 3 * grp) * F2W + 4 * tx;

#pragma unroll 1
    for (int st = 0; st < NSTG; ++st) {
        asm volatile("cp.async.wait_group 1;" ::: "memory");
        __syncthreads();

        // stage st+2 into buffer (st+2)%3 (its readers finished before the barrier)
        if (st + 2 < NSTG) issue(st + 2, (st + 2) % 3);
        asm volatile("cp.async.commit_group;" ::: "memory");

        const int buf = st % 3;
#pragma unroll
        for (int cc = 0; cc < CPS; ++cc) {
            const float* slot = &smem[(buf * CPS + cc) * CHSZ];
            const float4 f1v = *(const float4*)(slot + f1off);    // LDS.128
            const float* base = slot + f2off;
#pragma unroll
            for (int ii = 0; ii < 3; ++ii) {
                const float* wr = base + ii * F2W;
                float w[12];
                *(float4*)&w[0] = *(const float4*)(wr);       // LDS.128, conflict-free
                *(float4*)&w[4] = *(const float4*)(wr + 4);
                *(float4*)&w[8] = *(const float4*)(wr + 8);
#pragma unroll
                for (int j = 0; j < Ss; ++j) {
                    acc[ii * 36 + j * 4 + 0] = fmaf(f1v.x, w[j + 0], acc[ii * 36 + j * 4 + 0]);
                    acc[ii * 36 + j * 4 + 1] = fmaf(f1v.y, w[j + 1], acc[ii * 36 + j * 4 + 1]);
                    acc[ii * 36 + j * 4 + 2] = fmaf(f1v.z, w[j + 2], acc[ii * 36 + j * 4 + 2]);
                    acc[ii * 36 + j * 4 + 3] = fmaf(f1v.w, w[j + 3], acc[ii * 36 + j * 4 + 3]);
                }
            }
        }
    }

    // ---- epilogue: 27 float4 stores per thread, coalesced ----
    const float sc = 1.0f / (float)Cc;
    float* ob = out + (((size_t)b * NS) * Hc + (h0 + r)) * (size_t)Wc + (w0 + 4 * tx);
#pragma unroll
    for (int ii = 0; ii < 3; ++ii) {
#pragma unroll
        for (int j = 0; j < Ss; ++j) {
            const int s = (3 * grp + ii) * Ss + j;
            float4 v;
            v.x = acc[ii * 36 + j * 4 + 0] * sc;
            v.y = acc[ii * 36 + j * 4 + 1] * sc;
            v.z = acc[ii * 36 + j * 4 + 2] * sc;
            v.w = acc[ii * 36 + j * 4 + 3] * sc;
            *(float4*)(ob + (size_t)s * HW) = v;
        }
    }
}

extern "C" void kernel_launch(void* const* d_in, const int* in_sizes, int n_in,
                              void* d_out, int out_size) {
    const float* f1 = (const float*)d_in[0];
    const float* f2 = (const float*)d_in[1];
    float* out = (float*)d_out;
    // host-side attribute set: idempotent, no allocation, graph-capture safe
    static bool attr_done = false;
    if (!attr_done) {
        cudaFuncSetAttribute(cost_volume_kernel,
                             cudaFuncAttributeMaxDynamicSharedMemorySize,
                             SMEM_BYTES);
        attr_done = true;
    }
    dim3 grid(Wc / TW, Hc / TH, Bc);   // 8 x 8 x 8 = 512 blocks
    cost_volume_kernel<<<grid, NT, SMEM_BYTES>>>(f1, f2, out);
}

// round 14
// speedup vs baseline: 1.6204x; 1.0810x over previous
#include <cuda_runtime.h>
#include <cstdint>

// Cost volume, B=8 C=128 H=128 W=256, d=4 -> 81 shifts.
// out[b, i*9+j, h, w] = (1/C) * sum_c f1[b,c,h,w] * f2[b,c,h+i-4,w+j-4] (zero pad)
//
// v13 = v9 (191us) with half-height tiles + 2 CTAs/SM:
//   - TH 16 -> 8, NT 384 -> 192, grid 512 -> 1024: kills the partial-wave
//     quantization (3.46 waves @1 CTA/SM -> 6.92 tiles/SM @2 CTAs/SM)
//   - TW=32 kept: preserves the single-row conflict-free LDS.128 phases
//   - __launch_bounds__(192,2), 43KB static smem/CTA (86KB/SM)
//   - inner loop / pipeline identical to v9 (32 stages x 4 channels)

namespace {
constexpr int Bc = 8;
constexpr int Cc = 128;
constexpr int Hc = 128;
constexpr int Wc = 256;
constexpr int Dd = 4;
constexpr int Ss = 9;
constexpr int NS = 81;
constexpr int TH = 8;
constexpr int TW = 32;
constexpr int F2H = TH + 2 * Dd;    // 16
constexpr int F2W = TW + 2 * Dd;    // 40 floats row stride (160B, 16B multiple)
constexpr int HW = Hc * Wc;
constexpr int NF2 = F2H * (F2W / 4);   // 160 float4 chunks per channel
constexpr int NF1 = TH * TW / 4;       // 64 float4 chunks per channel
constexpr int NT = 192;
constexpr int CPS = 4;                 // channels per stage
constexpr int NSTG = Cc / CPS;         // 32 stages
constexpr int F2SZ = F2H * F2W;        // 640 floats
constexpr int F1SZ = TH * TW;          // 256 floats
constexpr int CHSZ = F2SZ + F1SZ;      // 896 floats per channel slot
}

__global__ __launch_bounds__(NT, 2)
void cost_volume_kernel(const float* __restrict__ f1,
                        const float* __restrict__ f2,
                        float* __restrict__ out) {
    __shared__ __align__(16) float smem[3 * CPS * CHSZ];   // 43008 B
    // layout: slot(buf, cc) = smem + (buf*CPS + cc)*CHSZ ; f2 first, then f1

    const int tid = threadIdx.x;
    const int grp = tid / 64;           // i-group: handles i = 3*grp + ii
    const int gt  = tid % 64;
    const int tx  = gt & 7;             // quad column (w = w0 + 4*tx + p)
    const int r   = gt >> 3;            // output row within tile, 0..7
    const int w0 = blockIdx.x * TW;
    const int h0 = blockIdx.y * TH;
    const int b  = blockIdx.z;

    // ---- loader roles: tid<160 -> 1 f2 chunk, tid>=160 -> 2 f1 chunks ----
    const bool isF2 = (tid < NF2);
    size_t src0 = 0, src1 = 0; int sts0 = 0, sts1 = 0, srcsz = 16;
    if (isF2) {
        const int lr = tid / 10, lc = tid % 10;
        const int gh = h0 - Dd + lr;
        const int gw = w0 - Dd + 4 * lc;          // 4-aligned; halo chunks fully in/out
        const bool valid = ((unsigned)gh < (unsigned)Hc) &&
                           ((unsigned)gw < (unsigned)Wc);
        src0  = (((size_t)b * Cc) * Hc + (valid ? gh : 0)) * (size_t)Wc
              + (valid ? gw : 0);
        sts0  = lr * F2W + 4 * lc;                // within f2 part of slot
        srcsz = valid ? 16 : 0;                   // 0 -> zero-fill (padding)
    } else {
        const int L0 = tid - NF2;                 // 0..31, chunks L0 and L0+32
        int c = L0, lr = c >> 3, lc = c & 7;
        src0 = (((size_t)b * Cc) * Hc + (h0 + lr)) * (size_t)Wc + (w0 + 4 * lc);
        sts0 = F2SZ + lr * TW + 4 * lc;
        c = L0 + 32; lr = c >> 3; lc = c & 7;
        src1 = (((size_t)b * Cc) * Hc + (h0 + lr)) * (size_t)Wc + (w0 + 4 * lc);
        sts1 = F2SZ + lr * TW + 4 * lc;
    }

    // stage st = channels [CPS*st, CPS*st+CPS) into buffer buf
    auto issue = [&](int st, int buf) {
        if (isF2) {
            const float* s0 = f2 + src0 + (size_t)(CPS * st) * HW;
#pragma unroll
            for (int cc = 0; cc < CPS; ++cc) {
                uint32_t d = (uint32_t)__cvta_generic_to_shared(
                    &smem[(buf * CPS + cc) * CHSZ + sts0]);
                asm volatile("cp.async.cg.shared.global [%0], [%1], 16, %2;"
                             :: "r"(d), "l"(s0 + (size_t)cc * HW), "r"(srcsz));
            }
        } else {
            const float* a0 = f1 + src0 + (size_t)(CPS * st) * HW;
            const float* a1 = f1 + src1 + (size_t)(CPS * st) * HW;
#pragma unroll
            for (int cc = 0; cc < CPS; ++cc) {
                uint32_t d0 = (uint32_t)__cvta_generic_to_shared(
                    &smem[(buf * CPS + cc) * CHSZ + sts0]);
                uint32_t d1 = (uint32_t)__cvta_generic_to_shared(
                    &smem[(buf * CPS + cc) * CHSZ + sts1]);
                asm volatile("cp.async.cg.shared.global [%0], [%1], 16;"
                             :: "r"(d0), "l"(a0 + (size_t)cc * HW));
                asm volatile("cp.async.cg.shared.global [%0], [%1], 16;"
                             :: "r"(d1), "l"(a1 + (size_t)cc * HW));
            }
        }
    };

    // ---- prologue: stage 0 and 1 ----
    issue(0, 0);
    asm volatile("cp.async.commit_group;" ::: "memory");
    issue(1, 1);
    asm volatile("cp.async.commit_group;" ::: "memory");

    // 108 accumulators: acc[ii*36 + j*4 + p]
    float acc[108];
#pragma unroll
    for (int s = 0; s < 108; ++s) acc[s] = 0.0f;

    const int f1off = F2SZ + r * TW + 4 * tx;
    const int f2off = (r + 3 * grp) * F2W + 4 * tx;

#pragma unroll 1
    for (int st = 0; st < NSTG; ++st) {
        asm volatile("cp.async.wait_group 1;" ::: "memory");
        __syncthreads();

        // stage st+2 into buffer (st+2)%3 (its readers finished before the barrier)
        if (st + 2 < NSTG) issue(st + 2, (st + 2) % 3);
        asm volatile("cp.async.commit_group;" ::: "memory");

        const int buf = st % 3;
#pragma unroll
        for (int cc = 0; cc < CPS; ++cc) {
            const float* slot = &smem[(buf * CPS + cc) * CHSZ];
            const float4 f1v = *(const float4*)(slot + f1off);    // LDS.128
            const float* base = slot + f2off;
#pragma unroll
            for (int ii = 0; ii < 3; ++ii) {
                const float* wr = base + ii * F2W;
                float w[12];
                *(float4*)&w[0] = *(const float4*)(wr);       // LDS.128, conflict-free
                *(float4*)&w[4] = *(const float4*)(wr + 4);
                *(float4*)&w[8] = *(const float4*)(wr + 8);
#pragma unroll
                for (int j = 0; j < Ss; ++j) {
                    acc[ii * 36 + j * 4 + 0] = fmaf(f1v.x, w[j + 0], acc[ii * 36 + j * 4 + 0]);
                    acc[ii * 36 + j * 4 + 1] = fmaf(f1v.y, w[j + 1], acc[ii * 36 + j * 4 + 1]);
                    acc[ii * 36 + j * 4 + 2] = fmaf(f1v.z, w[j + 2], acc[ii * 36 + j * 4 + 2]);
                    acc[ii * 36 + j * 4 + 3] = fmaf(f1v.w, w[j + 3], acc[ii * 36 + j * 4 + 3]);
                }
            }
        }
    }

    // ---- epilogue: 27 float4 stores per thread, coalesced ----
    const float sc = 1.0f / (float)Cc;
    float* ob = out + (((size_t)b * NS) * Hc + (h0 + r)) * (size_t)Wc + (w0 + 4 * tx);
#pragma unroll
    for (int ii = 0; ii < 3; ++ii) {
#pragma unroll
        for (int j = 0; j < Ss; ++j) {
            const int s = (3 * grp + ii) * Ss + j;
            float4 v;
            v.x = acc[ii * 36 + j * 4 + 0] * sc;
            v.y = acc[ii * 36 + j * 4 + 1] * sc;
            v.z = acc[ii * 36 + j * 4 + 2] * sc;
            v.w = acc[ii * 36 + j * 4 + 3] * sc;
            *(float4*)(ob + (size_t)s * HW) = v;
        }
    }
}

extern "C" void kernel_launch(void* const* d_in, const int* in_sizes, int n_in,
                              void* d_out, int out_size) {
    const float* f1 = (const float*)d_in[0];
    const float* f2 = (const float*)d_in[1];
    float* out = (float*)d_out;
    dim3 grid(Wc / TW, Hc / TH, Bc);   // 8 x 16 x 8 = 1024 blocks
    cost_volume_kernel<<<grid, NT>>>(f1, f2, out);
}

// round 15
// speedup vs baseline: 1.7649x; 1.0892x over previous
#include <cuda_runtime.h>
#include <cstdint>

// Cost volume, B=8 C=128 H=128 W=256, d=4 -> 81 shifts.
// out[b, i*9+j, h, w] = (1/C) * sum_c f1[b,c,h,w] * f2[b,c,h+i-4,w+j-4] (zero pad)
//
// v14 = v13 (176.6us) with tighter pipeline mechanics:
//   - 4 smem buffers, stage loop unrolled x4 -> buffer index is a compile-time
//     constant (immediate smem offsets, no mod-3 IMAD chains)
//   - wait_group 2: 3 stages in flight, post-barrier reads guaranteed resident
//   - otherwise identical: TH=8/TW=32 tiles, 192 thr, 2 CTAs/SM, CPS=4,
//     scalar FFMA only

namespace {
constexpr int Bc = 8;
constexpr int Cc = 128;
constexpr int Hc = 128;
constexpr int Wc = 256;
constexpr int Dd = 4;
constexpr int Ss = 9;
constexpr int NS = 81;
constexpr int TH = 8;
constexpr int TW = 32;
constexpr int F2H = TH + 2 * Dd;    // 16
constexpr int F2W = TW + 2 * Dd;    // 40 floats row stride (160B, 16B multiple)
constexpr int HW = Hc * Wc;
constexpr int NF2 = F2H * (F2W / 4);   // 160 float4 chunks per channel
constexpr int NT = 192;
constexpr int CPS = 4;                 // channels per stage
constexpr int NSTG = Cc / CPS;         // 32 stages (divisible by 4)
constexpr int NBUF = 4;
constexpr int F2SZ = F2H * F2W;        // 640 floats
constexpr int F1SZ = TH * TW;          // 256 floats
constexpr int CHSZ = F2SZ + F1SZ;      // 896 floats per channel slot
constexpr int SMEM_BYTES = NBUF * CPS * CHSZ * 4;   // 57344 B
}

struct LoaderCtx {
    size_t src0, src1;
    int sts0, sts1, srcsz;
    bool isF2;
};

__device__ __forceinline__ void issue_stage(float* __restrict__ smem,
                                            const float* __restrict__ f1,
                                            const float* __restrict__ f2,
                                            const LoaderCtx& L, int st, int buf) {
    if (L.isF2) {
        const float* s0 = f2 + L.src0 + (size_t)(CPS * st) * HW;
#pragma unroll
        for (int cc = 0; cc < CPS; ++cc) {
            uint32_t d = (uint32_t)__cvta_generic_to_shared(
                &smem[(buf * CPS + cc) * CHSZ + L.sts0]);
            asm volatile("cp.async.cg.shared.global [%0], [%1], 16, %2;"
                         :: "r"(d), "l"(s0 + (size_t)cc * HW), "r"(L.srcsz));
        }
    } else {
        const float* a0 = f1 + L.src0 + (size_t)(CPS * st) * HW;
        const float* a1 = f1 + L.src1 + (size_t)(CPS * st) * HW;
#pragma unroll
        for (int cc = 0; cc < CPS; ++cc) {
            uint32_t d0 = (uint32_t)__cvta_generic_to_shared(
                &smem[(buf * CPS + cc) * CHSZ + L.sts0]);
            uint32_t d1 = (uint32_t)__cvta_generic_to_shared(
                &smem[(buf * CPS + cc) * CHSZ + L.sts1]);
            asm volatile("cp.async.cg.shared.global [%0], [%1], 16;"
                         :: "r"(d0), "l"(a0 + (size_t)cc * HW));
            asm volatile("cp.async.cg.shared.global [%0], [%1], 16;"
                         :: "r"(d1), "l"(a1 + (size_t)cc * HW));
        }
    }
}

template <int BUF>
__device__ __forceinline__ void compute_stage(const float* __restrict__ smem,
                                              int f1off, int f2off,
                                              float* __restrict__ acc) {
#pragma unroll
    for (int cc = 0; cc < CPS; ++cc) {
        const float* slot = &smem[(BUF * CPS + cc) * CHSZ];   // immediate offset
        const float4 f1v = *(const float4*)(slot + f1off);    // LDS.128
        const float* base = slot + f2off;
#pragma unroll
        for (int ii = 0; ii < 3; ++ii) {
            const float* wr = base + ii * F2W;
            float w[12];
            *(float4*)&w[0] = *(const float4*)(wr);       // LDS.128, conflict-free
            *(float4*)&w[4] = *(const float4*)(wr + 4);
            *(float4*)&w[8] = *(const float4*)(wr + 8);
#pragma unroll
            for (int j = 0; j < Ss; ++j) {
                acc[ii * 36 + j * 4 + 0] = fmaf(f1v.x, w[j + 0], acc[ii * 36 + j * 4 + 0]);
                acc[ii * 36 + j * 4 + 1] = fmaf(f1v.y, w[j + 1], acc[ii * 36 + j * 4 + 1]);
                acc[ii * 36 + j * 4 + 2] = fmaf(f1v.z, w[j + 2], acc[ii * 36 + j * 4 + 2]);
                acc[ii * 36 + j * 4 + 3] = fmaf(f1v.w, w[j + 3], acc[ii * 36 + j * 4 + 3]);
            }
        }
    }
}

__global__ __launch_bounds__(NT, 2)
void cost_volume_kernel(const float* __restrict__ f1,
                        const float* __restrict__ f2,
                        float* __restrict__ out) {
    extern __shared__ __align__(16) float smem[];
    // layout: slot(buf, cc) = smem + (buf*CPS + cc)*CHSZ ; f2 first, then f1

    const int tid = threadIdx.x;
    const int grp = tid / 64;           // i-group: handles i = 3*grp + ii
    const int gt  = tid % 64;
    const int tx  = gt & 7;             // quad column (w = w0 + 4*tx + p)
    const int r   = gt >> 3;            // output row within tile, 0..7
    const int w0 = blockIdx.x * TW;
    const int h0 = blockIdx.y * TH;
    const int b  = blockIdx.z;

    // ---- loader roles: tid<160 -> 1 f2 chunk, tid>=160 -> 2 f1 chunks ----
    LoaderCtx L;
    L.isF2 = (tid < NF2);
    L.src0 = 0; L.src1 = 0; L.sts0 = 0; L.sts1 = 0; L.srcsz = 16;
    if (L.isF2) {
        const int lr = tid / 10, lc = tid % 10;
        const int gh = h0 - Dd + lr;
        const int gw = w0 - Dd + 4 * lc;          // 4-aligned; halo chunks fully in/out
        const bool valid = ((unsigned)gh < (unsigned)Hc) &&
                           ((unsigned)gw < (unsigned)Wc);
        L.src0  = (((size_t)b * Cc) * Hc + (valid ? gh : 0)) * (size_t)Wc
                + (valid ? gw : 0);
        L.sts0  = lr * F2W + 4 * lc;              // within f2 part of slot
        L.srcsz = valid ? 16 : 0;                 // 0 -> zero-fill (padding)
    } else {
        const int L0 = tid - NF2;                 // 0..31, chunks L0 and L0+32
        int c = L0, lr = c >> 3, lc = c & 7;
        L.src0 = (((size_t)b * Cc) * Hc + (h0 + lr)) * (size_t)Wc + (w0 + 4 * lc);
        L.sts0 = F2SZ + lr * TW + 4 * lc;
        c = L0 + 32; lr = c >> 3; lc = c & 7;
        L.src1 = (((size_t)b * Cc) * Hc + (h0 + lr)) * (size_t)Wc + (w0 + 4 * lc);
        L.sts1 = F2SZ + lr * TW + 4 * lc;
    }

    // ---- prologue: stage 0, 1, 2 in flight ----
    issue_stage(smem, f1, f2, L, 0, 0);
    asm volatile("cp.async.commit_group;" ::: "memory");
    issue_stage(smem, f1, f2, L, 1, 1);
    asm volatile("cp.async.commit_group;" ::: "memory");
    issue_stage(smem, f1, f2, L, 2, 2);
    asm volatile("cp.async.commit_group;" ::: "memory");

    // 108 accumulators: acc[ii*36 + j*4 + p]
    float acc[108];
#pragma unroll
    for (int s = 0; s < 108; ++s) acc[s] = 0.0f;

    const int f1off = F2SZ + r * TW + 4 * tx;
    const int f2off = (r + 3 * grp) * F2W + 4 * tx;

#pragma unroll 1
    for (int st4 = 0; st4 < NSTG; st4 += 4) {
#pragma unroll
        for (int u = 0; u < 4; ++u) {
            const int st = st4 + u;
            asm volatile("cp.async.wait_group 2;" ::: "memory");
            __syncthreads();
            // stage st+3 -> buffer (st+3)%4; its readers finished at stage st-1,
            // i.e. before the barrier above.
            if (st + 3 < NSTG)
                issue_stage(smem, f1, f2, L, st + 3, (st + 3) & 3);
            asm volatile("cp.async.commit_group;" ::: "memory");

            switch (u) {                 // buf = st & 3 = u (st4 multiple of 4)
                case 0: compute_stage<0>(smem, f1off, f2off, acc); break;
                case 1: compute_stage<1>(smem, f1off, f2off, acc); break;
                case 2: compute_stage<2>(smem, f1off, f2off, acc); break;
                case 3: compute_stage<3>(smem, f1off, f2off, acc); break;
            }
        }
    }

    // ---- epilogue: 27 float4 stores per thread, coalesced ----
    const float sc = 1.0f / (float)Cc;
    float* ob = out + (((size_t)b * NS) * Hc + (h0 + r)) * (size_t)Wc + (w0 + 4 * tx);
#pragma unroll
    for (int ii = 0; ii < 3; ++ii) {
#pragma unroll
        for (int j = 0; j < Ss; ++j) {
            const int s = (3 * grp + ii) * Ss + j;
            float4 v;
            v.x = acc[ii * 36 + j * 4 + 0] * sc;
            v.y = acc[ii * 36 + j * 4 + 1] * sc;
            v.z = acc[ii * 36 + j * 4 + 2] * sc;
            v.w = acc[ii * 36 + j * 4 + 3] * sc;
            *(float4*)(ob + (size_t)s * HW) = v;
        }
    }
}

extern "C" void kernel_launch(void* const* d_in, const int* in_sizes, int n_in,
                              void* d_out, int out_size) {
    const float* f1 = (const float*)d_in[0];
    const float* f2 = (const float*)d_in[1];
    float* out = (float*)d_out;
    // host-side attribute set: idempotent, no allocation, graph-capture safe
    static bool attr_done = false;
    if (!attr_done) {
        cudaFuncSetAttribute(cost_volume_kernel,
                             cudaFuncAttributeMaxDynamicSharedMemorySize,
                             SMEM_BYTES);
        attr_done = true;
    }
    dim3 grid(Wc / TW, Hc / TH, Bc);   // 8 x 16 x 8 = 1024 blocks
    cost_volume_kernel<<<grid, NT, SMEM_BYTES>>>(f1, f2, out);
}